// round 1
// baseline (speedup 1.0000x reference)
#include <cuda_runtime.h>

// Problem constants
#define NB   2
#define CC   256
#define NHD  8
#define HD   32
#define WD   32
#define HW   1024
#define WS   15
#define WS2  225
#define INVT 0.17677669529663687f

// k-tile smem geometry (padded strides for bank-conflict avoidance / alignment)
#define XSTR   36            // per-pixel channel stride (floats), 16B aligned
#define RSTR   1156          // per-dy-row stride (32*36 + 4) to spread banks
#define KSH_SZ (15*RSTR)     // 17340 floats
#define ASH_SZ (32*233)      // 7456 floats  (attn buffer, stride 233 coprime w/ 32)
#define RVSH_SZ (WS2*XSTR)   // 8100 floats
#define ATTN_SMEM ((KSH_SZ + ASH_SZ + RVSH_SZ)*4)  // 131584 bytes

// Scratch (device globals; allocation-free)
__device__ float g_qT[NB*NHD*HW*HD];     // [nh][p][c]
__device__ float g_kT[NB*NHD*HW*HD];     // [nh][p][c]  (pre-scaled by 1/T)
__device__ float g_vT[NB*NHD*HW*HD];     // [nh][p][c]
__device__ float g_rel[NB*NHD*WS2*HW];   // [nh][s][p]
__device__ float g_O[CC*NB*HW];          // [c][r], r = p*NB + n
__device__ float g_attn_fallback[NB*NHD*WS2*HW];

// ---------------------------------------------------------------------------
// Kernel 1: Q/K/V 1x1-conv projections.  Y[o,p] = sum_c W[o,c]*X[c,p] + b[o]
// Output transposed to [nh][p][c] (c = o%32 within head h = o/32).
// Tile: 32 o x 64 p, 256 threads, each thread 4o x 2p.
// ---------------------------------------------------------------------------
__global__ __launch_bounds__(256) void proj_kernel(
    const float* __restrict__ q, const float* __restrict__ k, const float* __restrict__ v,
    const float* __restrict__ WQ, const float* __restrict__ bQ,
    const float* __restrict__ WK, const float* __restrict__ bK,
    const float* __restrict__ WV, const float* __restrict__ bV)
{
    __shared__ float Xs[32*64];
    __shared__ float Ws[32*36];

    int which = blockIdx.z >> 1;       // 0=q 1=k 2=v
    int n     = blockIdx.z & 1;
    const float* X; const float* W; const float* b; float* out; float scale;
    if (which == 0)      { X = q; W = WQ; b = bQ; out = g_qT; scale = 1.0f; }
    else if (which == 1) { X = k; W = WK; b = bK; out = g_kT; scale = INVT; }
    else                 { X = v; W = WV; b = bV; out = g_vT; scale = 1.0f; }
    X   += (size_t)n * CC * HW;
    out += (size_t)n * NHD * HW * HD;

    int tid = threadIdx.x;
    int pi  = tid & 31, oi = tid >> 5;
    int p0  = blockIdx.x * 64;
    int h   = blockIdx.y;              // o-tile == head
    int o0  = h * 32;

    float4 acc0 = {0.f,0.f,0.f,0.f};
    float4 acc1 = {0.f,0.f,0.f,0.f};

    for (int ck = 0; ck < CC; ck += 32) {
        #pragma unroll
        for (int i = 0; i < 8; i++) {
            int idx = tid + i*256;
            int c = idx >> 6, pp = idx & 63;
            Xs[c*64 + pp] = X[(ck + c)*HW + p0 + pp];
        }
        #pragma unroll
        for (int i = 0; i < 4; i++) {
            int idx = tid + i*256;
            int o = idx >> 5, c = idx & 31;
            Ws[c*36 + o] = W[(o0 + o)*CC + ck + c] * scale;
        }
        __syncthreads();
        #pragma unroll
        for (int c = 0; c < 32; c++) {
            float xv0 = Xs[c*64 + pi];
            float xv1 = Xs[c*64 + pi + 32];
            float4 w4 = *(const float4*)&Ws[c*36 + oi*4];
            acc0.x += w4.x*xv0; acc0.y += w4.y*xv0; acc0.z += w4.z*xv0; acc0.w += w4.w*xv0;
            acc1.x += w4.x*xv1; acc1.y += w4.y*xv1; acc1.z += w4.z*xv1; acc1.w += w4.w*xv1;
        }
        __syncthreads();
    }
    float b0 = b[o0 + oi*4 + 0]*scale, b1 = b[o0 + oi*4 + 1]*scale;
    float b2 = b[o0 + oi*4 + 2]*scale, b3 = b[o0 + oi*4 + 3]*scale;
    acc0.x += b0; acc0.y += b1; acc0.z += b2; acc0.w += b3;
    acc1.x += b0; acc1.y += b1; acc1.z += b2; acc1.w += b3;
    *(float4*)&out[((size_t)h*HW + p0 + pi     )*HD + oi*4] = acc0;
    *(float4*)&out[((size_t)h*HW + p0 + pi + 32)*HD + oi*4] = acc1;
}

// ---------------------------------------------------------------------------
// Kernel 2: relative position logits.
// rel[nh][s][p] = sum_c qT[nh][p][c] * Wrk[h][s][c] + brk[h][s]
// Per block: one (nh), 64-pixel tile, all 225 taps. Thread: 4s x 4p.
// ---------------------------------------------------------------------------
__global__ __launch_bounds__(256) void rel_kernel(
    const float* __restrict__ Wrk, const float* __restrict__ brk)
{
    __shared__ float wsh[WS2*36];   // [s][c] stride 36
    __shared__ float qsh[64*36];    // [p][c] stride 36

    int nh = blockIdx.y;
    int h  = nh & 7;
    int p0 = blockIdx.x * 64;
    int tid = threadIdx.x;

    for (int idx = tid; idx < WS2*8; idx += 256) {
        int s = idx >> 3, cc = idx & 7;
        *(float4*)&wsh[s*36 + cc*4] = *(const float4*)&Wrk[((size_t)h*WS2 + s)*HD + cc*4];
    }
    for (int idx = tid; idx < 64*8; idx += 256) {
        int pp = idx >> 3, cc = idx & 7;
        *(float4*)&qsh[pp*36 + cc*4] = *(const float4*)&g_qT[((size_t)nh*HW + p0 + pp)*HD + cc*4];
    }
    __syncthreads();

    int pg = tid & 15;      // 4 pixels: p0 + pg*4 ..
    int sg = tid >> 4;      // s base: sg*4 + rep*64
    for (int rep = 0; rep < 4; rep++) {
        int sb = sg*4 + rep*64;
        if (sb >= WS2) break;
        float acc[4][4];
        #pragma unroll
        for (int j = 0; j < 4; j++)
            #pragma unroll
            for (int i = 0; i < 4; i++) acc[j][i] = 0.f;
        #pragma unroll
        for (int cc = 0; cc < 8; cc++) {
            float4 qv[4], wv[4];
            #pragma unroll
            for (int i = 0; i < 4; i++) qv[i] = *(const float4*)&qsh[(pg*4 + i)*36 + cc*4];
            #pragma unroll
            for (int j = 0; j < 4; j++) {
                if (sb + j < WS2) wv[j] = *(const float4*)&wsh[(sb + j)*36 + cc*4];
                else              wv[j] = make_float4(0.f,0.f,0.f,0.f);
            }
            #pragma unroll
            for (int j = 0; j < 4; j++)
                #pragma unroll
                for (int i = 0; i < 4; i++)
                    acc[j][i] += qv[i].x*wv[j].x + qv[i].y*wv[j].y
                               + qv[i].z*wv[j].z + qv[i].w*wv[j].w;
        }
        #pragma unroll
        for (int j = 0; j < 4; j++) {
            if (sb + j < WS2) {
                float bv = brk[h*WS2 + sb + j];
                float4 r4 = make_float4(acc[j][0]+bv, acc[j][1]+bv, acc[j][2]+bv, acc[j][3]+bv);
                *(float4*)&g_rel[((size_t)nh*WS2 + sb + j)*HW + p0 + pg*4] = r4;
            }
        }
    }
}

// ---------------------------------------------------------------------------
// Kernel 3: local attention. Block = (y, h, n). 256 threads.
// Pass A: qk = q.(k*invT) + rel, masked -> -1e8; softmax over 225 taps.
// Pass B: out[c] = sum_s attn_s * (v_nb + rel_v[h][c][s]).
// ---------------------------------------------------------------------------
__global__ __launch_bounds__(256) void attn_kernel(
    const float* __restrict__ rel_v, float* __restrict__ attn_out)
{
    extern __shared__ float sm[];
    float* ksh  = sm;                       // 15 x 32 x 36 (dy stride RSTR)
    float* ash  = sm + KSH_SZ;              // [x][s] stride 233
    float* rvsh = sm + KSH_SZ + ASH_SZ;     // [s][c] stride 36

    if (attn_out == nullptr) attn_out = g_attn_fallback;

    int y = blockIdx.x, h = blockIdx.y, n = blockIdx.z;
    int nh = n*NHD + h;
    int tid = threadIdx.x;

    // ---- load K neighborhood tile (15 rows) ----
    const float* kbase = g_kT + (size_t)nh*HW*HD;
    for (int i = tid; i < 15*256; i += 256) {
        int r = i >> 8, j = i & 255;
        int gy = y + r - 7;
        if ((unsigned)gy < 32u) {
            int xx = j >> 3, cc = j & 7;
            *(float4*)&ksh[r*RSTR + xx*XSTR + cc*4] =
                *(const float4*)&kbase[((size_t)gy*32 + xx)*HD + cc*4];
        }
    }

    int x   = tid >> 3;          // pixel in row
    int sub = tid & 7;           // 8 threads per pixel
    int p   = y*32 + x;

    float4 ql[8];
    {
        const float* qb = g_qT + ((size_t)nh*HW + p)*HD;
        #pragma unroll
        for (int i = 0; i < 8; i++) ql[i] = *(const float4*)&qb[i*4];
    }
    __syncthreads();

    // ---- pass A: qk + max ----
    const float* relb = g_rel + (size_t)nh*WS2*HW + p;
    float m = -3.0e38f;
    for (int s = sub; s < WS2; s += 8) {
        int r = s / 15;
        int dxx = s - r*15;
        int gy = y + r - 7;
        int xx = x + dxx - 7;
        float val;
        if ((unsigned)gy < 32u && (unsigned)xx < 32u) {
            const float* kr = &ksh[r*RSTR + xx*XSTR];
            float acc = 0.f;
            #pragma unroll
            for (int i = 0; i < 8; i++) {
                float4 kv = *(const float4*)&kr[i*4];
                acc += ql[i].x*kv.x + ql[i].y*kv.y + ql[i].z*kv.z + ql[i].w*kv.w;
            }
            val = acc + relb[(size_t)s*HW];
        } else {
            val = -1.0e8f;
        }
        ash[x*233 + s] = val;
        m = fmaxf(m, val);
    }
    m = fmaxf(m, __shfl_xor_sync(0xffffffffu, m, 1));
    m = fmaxf(m, __shfl_xor_sync(0xffffffffu, m, 2));
    m = fmaxf(m, __shfl_xor_sync(0xffffffffu, m, 4));

    float lsum = 0.f;
    for (int s = sub; s < WS2; s += 8) {
        float e = __expf(ash[x*233 + s] - m);
        ash[x*233 + s] = e;
        lsum += e;
    }
    lsum += __shfl_xor_sync(0xffffffffu, lsum, 1);
    lsum += __shfl_xor_sync(0xffffffffu, lsum, 2);
    lsum += __shfl_xor_sync(0xffffffffu, lsum, 4);
    float rinv = 1.0f / lsum;
    for (int s = sub; s < WS2; s += 8) ash[x*233 + s] *= rinv;
    __syncthreads();

    // ---- coalesced attn write: attn[nh][s][p] ----
    {
        float* aout = attn_out + (size_t)nh*WS2*HW + y*32;
        for (int i = tid; i < WS2*32; i += 256) {
            int s = i >> 5, x2 = i & 31;
            aout[(size_t)s*HW + x2] = ash[x2*233 + s];
        }
    }

    // ---- load V tile (overwrites ksh; safe: pass-A reads finished pre-barrier) ----
    const float* vbase = g_vT + (size_t)nh*HW*HD;
    for (int i = tid; i < 15*256; i += 256) {
        int r = i >> 8, j = i & 255;
        int gy = y + r - 7;
        if ((unsigned)gy < 32u) {
            int xx = j >> 3, cc = j & 7;
            *(float4*)&ksh[r*RSTR + xx*XSTR + cc*4] =
                *(const float4*)&vbase[((size_t)gy*32 + xx)*HD + cc*4];
        }
    }
    // rel_v[h][c][s] -> rvsh[s][c]
    for (int i = tid; i < WS2*32; i += 256) {
        int c = i / WS2, s = i - c*WS2;
        rvsh[s*XSTR + c] = rel_v[((size_t)h*HD + c)*WS2 + s];
    }
    __syncthreads();

    // ---- pass B: out[c] = sum_s a * (v + rel_v) ----
    int xb = tid & 31, cg = tid >> 5;     // thread: pixel xb, channels cg*4..+3
    float4 acc = {0.f,0.f,0.f,0.f};
    const float* ar = &ash[xb*233];
    for (int r = 0; r < 15; r++) {
        int gy = y + r - 7;
        if ((unsigned)gy >= 32u) continue;
        #pragma unroll
        for (int dxx = 0; dxx < 15; dxx++) {
            int xx = xb + dxx - 7;
            if ((unsigned)xx < 32u) {
                int s = r*15 + dxx;
                float a = ar[s];
                float4 vv = *(const float4*)&ksh[r*RSTR + xx*XSTR + cg*4];
                float4 rv = *(const float4*)&rvsh[s*XSTR + cg*4];
                acc.x += a*(vv.x + rv.x);
                acc.y += a*(vv.y + rv.y);
                acc.z += a*(vv.z + rv.z);
                acc.w += a*(vv.w + rv.w);
            }
        }
    }
    // O[c_full][r], r = p*NB + n
    int cfull = h*HD + cg*4;
    int rr = (y*32 + xb)*NB + n;
    g_O[(size_t)(cfull+0)*(NB*HW) + rr] = acc.x;
    g_O[(size_t)(cfull+1)*(NB*HW) + rr] = acc.y;
    g_O[(size_t)(cfull+2)*(NB*HW) + rr] = acc.z;
    g_O[(size_t)(cfull+3)*(NB*HW) + rr] = acc.w;
}

// ---------------------------------------------------------------------------
// Kernel 4: final projection. Y[r][o] = sum_c O[c][r]*Wp[o][c] + bp[o]
// Same tiling as proj_kernel. Output written straight to d_out (hw, n, c).
// ---------------------------------------------------------------------------
__global__ __launch_bounds__(256) void final_kernel(
    const float* __restrict__ Wp, const float* __restrict__ bp, float* __restrict__ out)
{
    __shared__ float Xs[32*64];
    __shared__ float Ws[32*36];

    int tid = threadIdx.x;
    int pi  = tid & 31, oi = tid >> 5;
    int r0  = blockIdx.x * 64;
    int o0  = blockIdx.y * 32;
    const int R = NB*HW;

    float4 acc0 = {0.f,0.f,0.f,0.f};
    float4 acc1 = {0.f,0.f,0.f,0.f};

    for (int ck = 0; ck < CC; ck += 32) {
        #pragma unroll
        for (int i = 0; i < 8; i++) {
            int idx = tid + i*256;
            int c = idx >> 6, rr = idx & 63;
            Xs[c*64 + rr] = g_O[(size_t)(ck + c)*R + r0 + rr];
        }
        #pragma unroll
        for (int i = 0; i < 4; i++) {
            int idx = tid + i*256;
            int o = idx >> 5, c = idx & 31;
            Ws[c*36 + o] = Wp[(o0 + o)*CC + ck + c];
        }
        __syncthreads();
        #pragma unroll
        for (int c = 0; c < 32; c++) {
            float xv0 = Xs[c*64 + pi];
            float xv1 = Xs[c*64 + pi + 32];
            float4 w4 = *(const float4*)&Ws[c*36 + oi*4];
            acc0.x += w4.x*xv0; acc0.y += w4.y*xv0; acc0.z += w4.z*xv0; acc0.w += w4.w*xv0;
            acc1.x += w4.x*xv1; acc1.y += w4.y*xv1; acc1.z += w4.z*xv1; acc1.w += w4.w*xv1;
        }
        __syncthreads();
    }
    float4 b4 = *(const float4*)&bp[o0 + oi*4];
    acc0.x += b4.x; acc0.y += b4.y; acc0.z += b4.z; acc0.w += b4.w;
    acc1.x += b4.x; acc1.y += b4.y; acc1.z += b4.z; acc1.w += b4.w;
    *(float4*)&out[(size_t)(r0 + pi     )*CC + o0 + oi*4] = acc0;
    *(float4*)&out[(size_t)(r0 + pi + 32)*CC + o0 + oi*4] = acc1;
}

// ---------------------------------------------------------------------------
extern "C" void kernel_launch(void* const* d_in, const int* in_sizes, int n_in,
                              void* d_out, int out_size)
{
    const float* q     = (const float*)d_in[0];
    const float* k     = (const float*)d_in[1];
    const float* v     = (const float*)d_in[2];
    const float* WQ    = (const float*)d_in[3];
    const float* bQ    = (const float*)d_in[4];
    const float* WK    = (const float*)d_in[5];
    const float* bK    = (const float*)d_in[6];
    const float* WV    = (const float*)d_in[7];
    const float* bV    = (const float*)d_in[8];
    const float* Wrk   = (const float*)d_in[9];
    const float* brk   = (const float*)d_in[10];
    const float* rel_v = (const float*)d_in[11];
    const float* Wp    = (const float*)d_in[12];
    const float* bp    = (const float*)d_in[13];

    float* out = (float*)d_out;
    const int OUT_ELEMS  = HW*NB*CC;            // 524288
    const int ATTN_ELEMS = NB*NHD*WS2*HW;       // 3686400
    float* attn_out = (out_size >= OUT_ELEMS + ATTN_ELEMS) ? (out + OUT_ELEMS) : nullptr;

    cudaFuncSetAttribute(attn_kernel, cudaFuncAttributeMaxDynamicSharedMemorySize, ATTN_SMEM);

    proj_kernel<<<dim3(16, 8, 6), 256>>>(q, k, v, WQ, bQ, WK, bK, WV, bV);
    rel_kernel<<<dim3(16, NB*NHD), 256>>>(Wrk, brk);
    attn_kernel<<<dim3(32, NHD, NB), 256, ATTN_SMEM>>>(rel_v, attn_out);
    final_kernel<<<dim3(32, 8), 256>>>(Wp, bp, out);
}

// round 9
// speedup vs baseline: 1.3105x; 1.3105x over previous
#include <cuda_runtime.h>

typedef unsigned long long ull;

#define NB   2
#define CC   256
#define NHD  8
#define HD   32
#define HW   1024
#define WS2  225
#define INVT 0.17677669529663687f

// attention smem layout (floats)
#define JSTR   772                 // arena row stride (32 rows)
#define AR_QS  24704               // Qs [c][x] stride 36
#define AR_ASH 25856               // ash [s][x] stride 36
#define AR_BRK 33956               // brk 225 (pad 240)
#define AR_RVS 34196               // rel_v staged [s][c] stride 36
#define SM_FLOATS 42296
#define ATTN_SMEM (SM_FLOATS*4)    // 169184 B

// Scratch (device globals; allocation-free)
__device__ float g_qT[NB*NHD*HW*HD];   // [nh][p][c]  raw Q
__device__ float g_kT[NB*NHD*HW*HD];   // [nh][p][c]  K pre-scaled by 1/T
__device__ float g_vT[NB*NHD*HW*HD];   // [nh][p][c]
__device__ float g_O[CC*NB*HW];        // [c][r], r = p*NB + n
__device__ float g_attn_fallback[NB*NHD*WS2*HW];
__device__ int   g_relv_nz;

// ---- f32x2 helpers -------------------------------------------------------
__device__ __forceinline__ ull pk2(float a, float b) {
    ull r; asm("mov.b64 %0, {%1, %2};" : "=l"(r) : "f"(a), "f"(b)); return r;
}
__device__ __forceinline__ void fma2(ull& d, ull a, ull b) {
    asm("fma.rn.f32x2 %0, %1, %2, %3;" : "=l"(d) : "l"(a), "l"(b), "l"(d));
}
__device__ __forceinline__ float2 upk(ull a) {
    float2 f; asm("mov.b64 {%0, %1}, %2;" : "=f"(f.x), "=f"(f.y) : "l"(a)); return f;
}

// ---------------------------------------------------------------------------
// rel_v nonzero detector (rel_v is zeros in the reference init; skip its
// pass-B term when it is). Deterministic, unconditional single write.
// ---------------------------------------------------------------------------
__global__ void relv_flag_kernel(const float* __restrict__ rel_v) {
    int nz = 0;
    const int total = NHD*HD*WS2;
    for (int i = threadIdx.x; i < total; i += blockDim.x)
        nz |= (rel_v[i] != 0.0f);
    int any = __syncthreads_or(nz);
    if (threadIdx.x == 0) g_relv_nz = any;
}

// ---------------------------------------------------------------------------
// Q/K/V 1x1 projections: C[o,p] = W[o,:]·X[:,p] + b[o], transposed store to
// [nh][p][c]. Tile 64x64, microtile 4ox4p in f32x2, K-chunk 64.
// K weights AND bias pre-scaled by 1/T (bugfix R6: weights were unscaled).
// ---------------------------------------------------------------------------
__global__ __launch_bounds__(256) void proj_kernel(
    const float* __restrict__ q, const float* __restrict__ k, const float* __restrict__ v,
    const float* __restrict__ WQ, const float* __restrict__ bQ,
    const float* __restrict__ WK, const float* __restrict__ bK,
    const float* __restrict__ WV, const float* __restrict__ bV)
{
    __shared__ float Xs[64*64];   // [c][p]
    __shared__ float Ws[64*68];   // [c][o]

    int which = blockIdx.z >> 1;
    int n     = blockIdx.z & 1;
    const float *X, *W, *B; float* out; float scale;
    if (which == 0)      { X = q; W = WQ; B = bQ; out = g_qT; scale = 1.0f; }
    else if (which == 1) { X = k; W = WK; B = bK; out = g_kT; scale = INVT; }
    else                 { X = v; W = WV; B = bV; out = g_vT; scale = 1.0f; }
    X   += (size_t)n * CC * HW;
    out += (size_t)n * NHD * HW * HD;

    int tid = threadIdx.x;
    int to = tid >> 4, tp = tid & 15;
    int p0 = blockIdx.x * 64;
    int o0 = blockIdx.y * 64;

    ull acc[4][2];
    #pragma unroll
    for (int i = 0; i < 4; i++) { acc[i][0] = 0ULL; acc[i][1] = 0ULL; }

    for (int ck = 0; ck < CC; ck += 64) {
        #pragma unroll
        for (int i = 0; i < 4; i++) {
            int idx = tid + i*256;
            int c = idx >> 4, pp = (idx & 15) * 4;
            *(float4*)&Xs[c*64 + pp] = *(const float4*)&X[(size_t)(ck + c)*HW + p0 + pp];
        }
        #pragma unroll
        for (int i = 0; i < 4; i++) {
            int idx = tid + i*256;
            int o = idx >> 4, c4 = (idx & 15) * 4;
            float4 w = *(const float4*)&W[(size_t)(o0 + o)*CC + ck + c4];
            Ws[(c4+0)*68 + o] = w.x * scale; Ws[(c4+1)*68 + o] = w.y * scale;
            Ws[(c4+2)*68 + o] = w.z * scale; Ws[(c4+3)*68 + o] = w.w * scale;
        }
        __syncthreads();
        #pragma unroll 8
        for (int c = 0; c < 64; c++) {
            float4 wv = *(const float4*)&Ws[c*68 + to*4];
            ulonglong2 xv = *(const ulonglong2*)&Xs[c*64 + tp*4];
            ull w0 = pk2(wv.x, wv.x), w1 = pk2(wv.y, wv.y);
            ull w2 = pk2(wv.z, wv.z), w3 = pk2(wv.w, wv.w);
            fma2(acc[0][0], w0, xv.x); fma2(acc[0][1], w0, xv.y);
            fma2(acc[1][0], w1, xv.x); fma2(acc[1][1], w1, xv.y);
            fma2(acc[2][0], w2, xv.x); fma2(acc[2][1], w2, xv.y);
            fma2(acc[3][0], w3, xv.x); fma2(acc[3][1], w3, xv.y);
        }
        __syncthreads();
    }

    float res[4][4];
    #pragma unroll
    for (int i = 0; i < 4; i++) {
        float bb = B[o0 + to*4 + i] * scale;
        float2 p01 = upk(acc[i][0]), p23 = upk(acc[i][1]);
        res[i][0] = p01.x + bb; res[i][1] = p01.y + bb;
        res[i][2] = p23.x + bb; res[i][3] = p23.y + bb;
    }
    int oo = o0 + to*4;
    int h = oo >> 5, c0 = oo & 31;
    #pragma unroll
    for (int pi = 0; pi < 4; pi++) {
        int p = p0 + tp*4 + pi;
        float4 f4 = make_float4(res[0][pi], res[1][pi], res[2][pi], res[3][pi]);
        *(float4*)&out[((size_t)h*HW + p)*HD + c0] = f4;
    }
}

// ---------------------------------------------------------------------------
// Local attention, one block per (y, h, n). 256 threads.
// Phase 1: GEMM C[32x768] = Q[32x32] x R^T, R columns = 480 K-vectors + 225 Wrk.
// Phase 2: band-gather + softmax. Phase 3: predicate-free attn·V.
// ---------------------------------------------------------------------------
__global__ __launch_bounds__(256) void attn_kernel(
    const float* __restrict__ Wrk, const float* __restrict__ brk,
    const float* __restrict__ rel_v, float* __restrict__ attn_out)
{
    extern __shared__ float sm[];
    float* arena = sm;            // Rs [c][j] -> qkA [x][j] -> V [jj][c]
    float* qs    = sm + AR_QS;    // [c][x] stride 36
    float* ashp  = sm + AR_ASH;   // [s][x] stride 36
    float* brks  = sm + AR_BRK;
    float* rvs   = sm + AR_RVS;   // [s][c] stride 36

    if (attn_out == nullptr) attn_out = g_attn_fallback;

    int y = blockIdx.x, h = blockIdx.y, n = blockIdx.z;
    int nh = n*NHD + h;
    int tid = threadIdx.x;
    int flag = g_relv_nz;

    const float* qbase = g_qT + ((size_t)nh*HW + (size_t)y*32)*HD;
    const float* kbase = g_kT + (size_t)nh*HW*HD;
    const float* vbase = g_vT + (size_t)nh*HW*HD;

    // Qs [c][x]
    {
        int x = tid >> 3, c4 = (tid & 7) * 4;
        float4 f = *(const float4*)&qbase[x*HD + c4];
        qs[(c4+0)*36 + x] = f.x; qs[(c4+1)*36 + x] = f.y;
        qs[(c4+2)*36 + x] = f.z; qs[(c4+3)*36 + x] = f.w;
    }
    // R: K-neighborhood columns j = r*32+xx (zero for invalid rows)
    for (int i = tid; i < 480*8; i += 256) {
        int j = i >> 3, c4 = (i & 7) * 4;
        int r = j >> 5, xx = j & 31;
        int gy = y + r - 7;
        float4 f = make_float4(0.f, 0.f, 0.f, 0.f);
        if ((unsigned)gy < 32u) f = *(const float4*)&kbase[(size_t)(gy*32 + xx)*HD + c4];
        arena[(c4+0)*JSTR + j] = f.x; arena[(c4+1)*JSTR + j] = f.y;
        arena[(c4+2)*JSTR + j] = f.z; arena[(c4+3)*JSTR + j] = f.w;
    }
    // R: Wrk columns j = 480+s
    for (int i = tid; i < WS2*8; i += 256) {
        int s = i >> 3, c4 = (i & 7) * 4;
        float4 f = *(const float4*)&Wrk[((size_t)h*WS2 + s)*HD + c4];
        int j = 480 + s;
        arena[(c4+0)*JSTR + j] = f.x; arena[(c4+1)*JSTR + j] = f.y;
        arena[(c4+2)*JSTR + j] = f.z; arena[(c4+3)*JSTR + j] = f.w;
    }
    if (tid < WS2) brks[tid] = brk[h*WS2 + tid];
    __syncthreads();

    // ---- GEMM: thread = (tx: 4 x-rows, tj: 24 j-cols in 3 chunks of 8) ----
    int tx = tid >> 5, tj = tid & 31;
    ull acc[4][12];
    #pragma unroll
    for (int a = 0; a < 4; a++)
        #pragma unroll
        for (int b2 = 0; b2 < 12; b2++) acc[a][b2] = 0ULL;

    #pragma unroll 4
    for (int c = 0; c < 32; c++) {
        float4 qv = *(const float4*)&qs[c*36 + tx*4];
        ull q0 = pk2(qv.x, qv.x), q1 = pk2(qv.y, qv.y);
        ull q2 = pk2(qv.z, qv.z), q3 = pk2(qv.w, qv.w);
        const float* rb = &arena[c*JSTR + tj*8];
        #pragma unroll
        for (int jj = 0; jj < 3; jj++) {
            ulonglong2 ra = *(const ulonglong2*)(rb + jj*256);
            ulonglong2 rc = *(const ulonglong2*)(rb + jj*256 + 4);
            fma2(acc[0][jj*4+0], q0, ra.x); fma2(acc[0][jj*4+1], q0, ra.y);
            fma2(acc[0][jj*4+2], q0, rc.x); fma2(acc[0][jj*4+3], q0, rc.y);
            fma2(acc[1][jj*4+0], q1, ra.x); fma2(acc[1][jj*4+1], q1, ra.y);
            fma2(acc[1][jj*4+2], q1, rc.x); fma2(acc[1][jj*4+3], q1, rc.y);
            fma2(acc[2][jj*4+0], q2, ra.x); fma2(acc[2][jj*4+1], q2, ra.y);
            fma2(acc[2][jj*4+2], q2, rc.x); fma2(acc[2][jj*4+3], q2, rc.y);
            fma2(acc[3][jj*4+0], q3, ra.x); fma2(acc[3][jj*4+1], q3, ra.y);
            fma2(acc[3][jj*4+2], q3, rc.x); fma2(acc[3][jj*4+3], q3, rc.y);
        }
    }
    __syncthreads();
    // write qk into arena (overwrites R)
    #pragma unroll
    for (int xi = 0; xi < 4; xi++) {
        float* row = &arena[(tx*4 + xi)*JSTR + tj*8];
        #pragma unroll
        for (int jj = 0; jj < 3; jj++) {
            *(ull*)(row + jj*256 + 0) = acc[xi][jj*4+0];
            *(ull*)(row + jj*256 + 2) = acc[xi][jj*4+1];
            *(ull*)(row + jj*256 + 4) = acc[xi][jj*4+2];
            *(ull*)(row + jj*256 + 6) = acc[xi][jj*4+3];
        }
    }
    __syncthreads();

    // ---- softmax over 225 taps, 8 threads per pixel ----
    {
        int sx = tid >> 3, sub = tid & 7;
        const float* qrow = &arena[sx*JSTR];
        float m = -3.0e38f;
        for (int s = sub; s < WS2; s += 8) {
            int r = s / 15, dx = s - r*15;
            int xx = sx + dx - 7, gy = y + r - 7;
            float val = -1.0e8f;
            if ((unsigned)xx < 32u && (unsigned)gy < 32u)
                val = qrow[r*32 + xx] + qrow[480 + s] + brks[s];
            ashp[s*36 + sx] = val;
            m = fmaxf(m, val);
        }
        m = fmaxf(m, __shfl_xor_sync(0xffffffffu, m, 1));
        m = fmaxf(m, __shfl_xor_sync(0xffffffffu, m, 2));
        m = fmaxf(m, __shfl_xor_sync(0xffffffffu, m, 4));
        float lsum = 0.f;
        for (int s = sub; s < WS2; s += 8) {
            float e = __expf(ashp[s*36 + sx] - m);
            ashp[s*36 + sx] = e;
            lsum += e;
        }
        lsum += __shfl_xor_sync(0xffffffffu, lsum, 1);
        lsum += __shfl_xor_sync(0xffffffffu, lsum, 2);
        lsum += __shfl_xor_sync(0xffffffffu, lsum, 4);
        float rinv = 1.0f / lsum;
        for (int s = sub; s < WS2; s += 8) ashp[s*36 + sx] *= rinv;
    }
    __syncthreads();

    // ---- attn global write + V fill (arena reuse, +7 zero-padded rows) ----
    {
        float* aout = attn_out + (size_t)nh*WS2*HW + y*32;
        for (int i = tid; i < WS2*32; i += 256) {
            int s = i >> 5, x2 = i & 31;
            aout[(size_t)s*HW + x2] = ashp[s*36 + x2];
        }
    }
    for (int i = tid; i < 494*8; i += 256) {
        int jj = i >> 3, c4 = (i & 7) * 4;
        float4 f = make_float4(0.f, 0.f, 0.f, 0.f);
        if (jj >= 7 && jj < 487) {
            int j = jj - 7;
            int r = j >> 5, xx = j & 31;
            int gy = y + r - 7;
            if ((unsigned)gy < 32u) f = *(const float4*)&vbase[(size_t)(gy*32 + xx)*HD + c4];
        }
        *(float4*)&arena[jj*36 + c4] = f;
    }
    if (flag) {
        for (int i = tid; i < HD*WS2; i += 256) {
            int c = i / WS2, s = i - c*WS2;
            rvs[s*36 + c] = rel_v[((size_t)h*HD + c)*WS2 + s];
        }
    }
    __syncthreads();

    // ---- pass B: out[c] = sum_taps a * v  (no predicates; a==0 on masked) ----
    {
        int xb = tid & 31, cg = tid >> 5;
        ull a0 = 0ULL, a1 = 0ULL;
        const float* vsb = &arena[xb*36 + cg*4];
        #pragma unroll
        for (int r = 0; r < 15; r++) {
            const float* ap = &ashp[r*15*36 + xb];
            const float* vp = vsb + (r*32)*36;
            #pragma unroll
            for (int dx = 0; dx < 15; dx++) {
                float a = ap[dx*36];
                ull a2 = pk2(a, a);
                ulonglong2 vv = *(const ulonglong2*)(vp + dx*36);
                fma2(a0, a2, vv.x); fma2(a1, a2, vv.y);
            }
        }
        if (flag) {
            for (int s = 0; s < WS2; s++) {
                float a = ashp[s*36 + xb];
                ull a2 = pk2(a, a);
                ulonglong2 rv = *(const ulonglong2*)&rvs[s*36 + cg*4];
                fma2(a0, a2, rv.x); fma2(a1, a2, rv.y);
            }
        }
        float2 o01 = upk(a0), o23 = upk(a1);
        int cfull = h*HD + cg*4;
        int rr = (y*32 + xb)*NB + n;
        g_O[(size_t)(cfull+0)*(NB*HW) + rr] = o01.x;
        g_O[(size_t)(cfull+1)*(NB*HW) + rr] = o01.y;
        g_O[(size_t)(cfull+2)*(NB*HW) + rr] = o23.x;
        g_O[(size_t)(cfull+3)*(NB*HW) + rr] = o23.y;
    }
}

// ---------------------------------------------------------------------------
// Final projection: Y[r][o] = Wp[o,:]·O[:,r] + bp[o], straight into d_out.
// ---------------------------------------------------------------------------
__global__ __launch_bounds__(256) void final_kernel(
    const float* __restrict__ Wp, const float* __restrict__ bp, float* __restrict__ outp)
{
    __shared__ float Xs[64*64];
    __shared__ float Ws[64*68];
    const int R = NB*HW;

    int tid = threadIdx.x;
    int to = tid >> 4, tp = tid & 15;
    int r0 = blockIdx.x * 64;
    int o0 = blockIdx.y * 64;

    ull acc[4][2];
    #pragma unroll
    for (int i = 0; i < 4; i++) { acc[i][0] = 0ULL; acc[i][1] = 0ULL; }

    for (int ck = 0; ck < CC; ck += 64) {
        #pragma unroll
        for (int i = 0; i < 4; i++) {
            int idx = tid + i*256;
            int c = idx >> 4, pp = (idx & 15) * 4;
            *(float4*)&Xs[c*64 + pp] = *(const float4*)&g_O[(size_t)(ck + c)*R + r0 + pp];
        }
        #pragma unroll
        for (int i = 0; i < 4; i++) {
            int idx = tid + i*256;
            int o = idx >> 4, c4 = (idx & 15) * 4;
            float4 w = *(const float4*)&Wp[(size_t)(o0 + o)*CC + ck + c4];
            Ws[(c4+0)*68 + o] = w.x; Ws[(c4+1)*68 + o] = w.y;
            Ws[(c4+2)*68 + o] = w.z; Ws[(c4+3)*68 + o] = w.w;
        }
        __syncthreads();
        #pragma unroll 8
        for (int c = 0; c < 64; c++) {
            float4 wv = *(const float4*)&Ws[c*68 + to*4];
            ulonglong2 xv = *(const ulonglong2*)&Xs[c*64 + tp*4];
            ull w0 = pk2(wv.x, wv.x), w1 = pk2(wv.y, wv.y);
            ull w2 = pk2(wv.z, wv.z), w3 = pk2(wv.w, wv.w);
            fma2(acc[0][0], w0, xv.x); fma2(acc[0][1], w0, xv.y);
            fma2(acc[1][0], w1, xv.x); fma2(acc[1][1], w1, xv.y);
            fma2(acc[2][0], w2, xv.x); fma2(acc[2][1], w2, xv.y);
            fma2(acc[3][0], w3, xv.x); fma2(acc[3][1], w3, xv.y);
        }
        __syncthreads();
    }

    float res[4][4];
    #pragma unroll
    for (int i = 0; i < 4; i++) {
        float bb = bp[o0 + to*4 + i];
        float2 p01 = upk(acc[i][0]), p23 = upk(acc[i][1]);
        res[i][0] = p01.x + bb; res[i][1] = p01.y + bb;
        res[i][2] = p23.x + bb; res[i][3] = p23.y + bb;
    }
    #pragma unroll
    for (int pi = 0; pi < 4; pi++) {
        int r = r0 + tp*4 + pi;
        float4 f4 = make_float4(res[0][pi], res[1][pi], res[2][pi], res[3][pi]);
        *(float4*)&outp[(size_t)r*CC + o0 + to*4] = f4;
    }
}

// ---------------------------------------------------------------------------
extern "C" void kernel_launch(void* const* d_in, const int* in_sizes, int n_in,
                              void* d_out, int out_size)
{
    const float* q     = (const float*)d_in[0];
    const float* k     = (const float*)d_in[1];
    const float* v     = (const float*)d_in[2];
    const float* WQ    = (const float*)d_in[3];
    const float* bQ    = (const float*)d_in[4];
    const float* WK    = (const float*)d_in[5];
    const float* bK    = (const float*)d_in[6];
    const float* WV    = (const float*)d_in[7];
    const float* bV    = (const float*)d_in[8];
    const float* Wrk   = (const float*)d_in[9];
    const float* brk   = (const float*)d_in[10];
    const float* rel_v = (const float*)d_in[11];
    const float* Wp    = (const float*)d_in[12];
    const float* bp    = (const float*)d_in[13];

    float* out = (float*)d_out;
    const int OUT_ELEMS  = HW*NB*CC;
    const int ATTN_ELEMS = NB*NHD*WS2*HW;
    float* attn_out = (out_size >= OUT_ELEMS + ATTN_ELEMS) ? (out + OUT_ELEMS) : nullptr;

    cudaFuncSetAttribute(attn_kernel, cudaFuncAttributeMaxDynamicSharedMemorySize, ATTN_SMEM);

    relv_flag_kernel<<<1, 1024>>>(rel_v);
    proj_kernel<<<dim3(16, 4, 6), 256>>>(q, k, v, WQ, bQ, WK, bK, WV, bV);
    attn_kernel<<<dim3(32, NHD, NB), 256, ATTN_SMEM>>>(Wrk, brk, rel_v, attn_out);
    final_kernel<<<dim3(32, 4), 256>>>(Wp, bp, out);
}

// round 10
// speedup vs baseline: 1.3683x; 1.0441x over previous
#include <cuda_runtime.h>

typedef unsigned long long ull;

#define NB   2
#define CC   256
#define NHD  8
#define HD   32
#define HW   1024
#define WS2  225
#define INVT 0.17677669529663687f

// attention smem layout (floats)
#define JSTR   772                 // arena row stride
#define AR_QS  24704               // Qs [c][x] stride 36 (reused as pass-B partial buffer)
#define AR_ASH 25856               // ash [s][x] stride 36
#define AR_BRK 33956               // brk 225 (pad 240)
#define AR_RVS 34196               // rel_v staged [s][c] stride 36
#define SM_FLOATS 42296
#define ATTN_SMEM (SM_FLOATS*4)    // 169184 B

// Scratch (device globals; allocation-free)
__device__ float g_qT[NB*NHD*HW*HD];   // [nh][p][c]
__device__ float g_kT[NB*NHD*HW*HD];   // [nh][p][c]  (pre-scaled by 1/T)
__device__ float g_vT[NB*NHD*HW*HD];   // [nh][p][c]
__device__ float g_O[CC*NB*HW];        // [c][r], r = p*NB + n
__device__ float g_attn_fallback[NB*NHD*WS2*HW];
__device__ int   g_relv_nz;

// ---- f32x2 helpers -------------------------------------------------------
__device__ __forceinline__ ull pk2(float a, float b) {
    ull r; asm("mov.b64 %0, {%1, %2};" : "=l"(r) : "f"(a), "f"(b)); return r;
}
__device__ __forceinline__ void fma2(ull& d, ull a, ull b) {
    asm("fma.rn.f32x2 %0, %1, %2, %3;" : "=l"(d) : "l"(a), "l"(b), "l"(d));
}
__device__ __forceinline__ float2 upk(ull a) {
    float2 f; asm("mov.b64 {%0, %1}, %2;" : "=f"(f.x), "=f"(f.y) : "l"(a)); return f;
}

// ---------------------------------------------------------------------------
__global__ void relv_flag_kernel(const float* __restrict__ rel_v) {
    const float4* rv4 = (const float4*)rel_v;
    const int total4 = NHD*HD*WS2/4;   // 14400
    int nz = 0;
    for (int i = threadIdx.x; i < total4; i += blockDim.x) {
        float4 f = rv4[i];
        nz |= (f.x != 0.f) | (f.y != 0.f) | (f.z != 0.f) | (f.w != 0.f);
    }
    int any = __syncthreads_or(nz);
    if (threadIdx.x == 0) g_relv_nz = any;
}

// ---------------------------------------------------------------------------
// Q/K/V projections. Tile 64o x 32p, 256 threads, microtile 2o x 4p (f32x2).
// Ws kept [o][c] (no transpose), Xs [c][p]. K-chunk 64. 25.4KB smem -> 4 CTA/SM.
// grid (32 p-tiles, 4 o-tiles, 6 = {q,k,v} x {n})
// ---------------------------------------------------------------------------
__global__ __launch_bounds__(256) void proj_kernel(
    const float* __restrict__ q, const float* __restrict__ k, const float* __restrict__ v,
    const float* __restrict__ WQ, const float* __restrict__ bQ,
    const float* __restrict__ WK, const float* __restrict__ bK,
    const float* __restrict__ WV, const float* __restrict__ bV)
{
    __shared__ float Xs[64*32];    // [c][p]
    __shared__ float Wso[64*68];   // [o][c] stride 68

    int which = blockIdx.z >> 1;
    int n     = blockIdx.z & 1;
    const float *X, *W, *B; float* out; float scale;
    if (which == 0)      { X = q; W = WQ; B = bQ; out = g_qT; scale = 1.0f; }
    else if (which == 1) { X = k; W = WK; B = bK; out = g_kT; scale = INVT; }
    else                 { X = v; W = WV; B = bV; out = g_vT; scale = 1.0f; }
    X   += (size_t)n * CC * HW;
    out += (size_t)n * NHD * HW * HD;

    int tid = threadIdx.x;
    int to = tid >> 3;            // 0..31 (o pair index)
    int tp = tid & 7;             // 0..7  (p quad index)
    int p0 = blockIdx.x * 32;
    int o0 = blockIdx.y * 64;

    ull acc[2][2] = {{0ULL,0ULL},{0ULL,0ULL}};

    for (int ck = 0; ck < CC; ck += 64) {
        #pragma unroll
        for (int i = 0; i < 2; i++) {
            int idx = tid + i*256;
            int c = idx >> 3, pp = (idx & 7) * 4;
            *(float4*)&Xs[c*32 + pp] = *(const float4*)&X[(size_t)(ck + c)*HW + p0 + pp];
        }
        #pragma unroll
        for (int i = 0; i < 4; i++) {
            int idx = tid + i*256;
            int o = idx >> 4, c4 = (idx & 15) * 4;
            float4 w = *(const float4*)&W[(size_t)(o0 + o)*CC + ck + c4];
            w.x *= scale; w.y *= scale; w.z *= scale; w.w *= scale;
            *(float4*)&Wso[o*68 + c4] = w;
        }
        __syncthreads();
        #pragma unroll 8
        for (int c = 0; c < 64; c++) {
            float w0 = Wso[(to*2+0)*68 + c];
            float w1 = Wso[(to*2+1)*68 + c];
            ulonglong2 xv = *(const ulonglong2*)&Xs[c*32 + tp*4];
            ull wp0 = pk2(w0, w0), wp1 = pk2(w1, w1);
            fma2(acc[0][0], wp0, xv.x); fma2(acc[0][1], wp0, xv.y);
            fma2(acc[1][0], wp1, xv.x); fma2(acc[1][1], wp1, xv.y);
        }
        __syncthreads();
    }

    float res[2][4];
    #pragma unroll
    for (int oi = 0; oi < 2; oi++) {
        float bb = B[o0 + to*2 + oi] * scale;
        float2 p01 = upk(acc[oi][0]), p23 = upk(acc[oi][1]);
        res[oi][0] = p01.x + bb; res[oi][1] = p01.y + bb;
        res[oi][2] = p23.x + bb; res[oi][3] = p23.y + bb;
    }
    int oo = o0 + to*2;
    int h = oo >> 5, c0 = oo & 31;
    #pragma unroll
    for (int pj = 0; pj < 4; pj++) {
        int p = p0 + tp*4 + pj;
        float2 f2 = make_float2(res[0][pj], res[1][pj]);
        *(float2*)&out[((size_t)h*HW + p)*HD + c0] = f2;
    }
}

// ---------------------------------------------------------------------------
// Local attention, one block per (y, h, n). 512 threads (16 warps).
// Phase 1: C[32x768] = Q[32x32] x R^T (R = 480 K-cols + 225 Wrk-cols),
//          thread = 2 x-rows x 24 j-cols (6 contiguous 4-col chunks).
// Phase 2: band-gather + softmax (16 thr/pixel).
// Phase 3: attn.V, tap-rows split across two 8-warp halves, smem combine.
// ---------------------------------------------------------------------------
__global__ __launch_bounds__(512) void attn_kernel(
    const float* __restrict__ Wrk, const float* __restrict__ brk,
    const float* __restrict__ rel_v, float* __restrict__ attn_out)
{
    extern __shared__ float sm[];
    float* arena = sm;            // R [c][j] -> qk [x][j] -> V [jj][c] (stride 36)
    float* qs    = sm + AR_QS;    // [c][x] stride 36; later pass-B partial buffer
    float* ashp  = sm + AR_ASH;   // [s][x] stride 36
    float* brks  = sm + AR_BRK;
    float* rvs   = sm + AR_RVS;   // [s][c] stride 36

    if (attn_out == nullptr) attn_out = g_attn_fallback;

    int y = blockIdx.x, h = blockIdx.y, n = blockIdx.z;
    int nh = n*NHD + h;
    int tid = threadIdx.x;
    int flag = g_relv_nz;

    const float* qbase = g_qT + ((size_t)nh*HW + (size_t)y*32)*HD;
    const float* kbase = g_kT + (size_t)nh*HW*HD;
    const float* vbase = g_vT + (size_t)nh*HW*HD;

    // Qs [c][x]
    if (tid < 256) {
        int x = tid >> 3, c4 = (tid & 7) * 4;
        float4 f = *(const float4*)&qbase[x*HD + c4];
        qs[(c4+0)*36 + x] = f.x; qs[(c4+1)*36 + x] = f.y;
        qs[(c4+2)*36 + x] = f.z; qs[(c4+3)*36 + x] = f.w;
    }
    // R: K-neighborhood columns j = r*32+xx (zero for invalid rows)
    for (int i = tid; i < 480*8; i += 512) {
        int j = i >> 3, c4 = (i & 7) * 4;
        int r = j >> 5, xx = j & 31;
        int gy = y + r - 7;
        float4 f = make_float4(0.f, 0.f, 0.f, 0.f);
        if ((unsigned)gy < 32u) f = *(const float4*)&kbase[(size_t)(gy*32 + xx)*HD + c4];
        arena[(c4+0)*JSTR + j] = f.x; arena[(c4+1)*JSTR + j] = f.y;
        arena[(c4+2)*JSTR + j] = f.z; arena[(c4+3)*JSTR + j] = f.w;
    }
    // R: Wrk columns j = 480+s
    for (int i = tid; i < WS2*8; i += 512) {
        int s = i >> 3, c4 = (i & 7) * 4;
        float4 f = *(const float4*)&Wrk[((size_t)h*WS2 + s)*HD + c4];
        int j = 480 + s;
        arena[(c4+0)*JSTR + j] = f.x; arena[(c4+1)*JSTR + j] = f.y;
        arena[(c4+2)*JSTR + j] = f.z; arena[(c4+3)*JSTR + j] = f.w;
    }
    if (tid < WS2) brks[tid] = brk[h*WS2 + tid];
    __syncthreads();

    // ---- phase 1 GEMM: tx 2 x-rows, tj 24 j-cols (6 chunks of 4, conflict-free)
    int tx = tid >> 5;       // 0..15
    int tj = tid & 31;       // 0..31
    ull acc[2][12];
    #pragma unroll
    for (int a = 0; a < 2; a++)
        #pragma unroll
        for (int b2 = 0; b2 < 12; b2++) acc[a][b2] = 0ULL;

    #pragma unroll 4
    for (int c = 0; c < 32; c++) {
        float2 qv = *(const float2*)&qs[c*36 + tx*2];
        ull q0 = pk2(qv.x, qv.x), q1 = pk2(qv.y, qv.y);
        const float* rb = &arena[c*JSTR + tj*4];
        #pragma unroll
        for (int cc = 0; cc < 6; cc++) {
            ulonglong2 rr = *(const ulonglong2*)(rb + cc*128);
            fma2(acc[0][cc*2+0], q0, rr.x); fma2(acc[0][cc*2+1], q0, rr.y);
            fma2(acc[1][cc*2+0], q1, rr.x); fma2(acc[1][cc*2+1], q1, rr.y);
        }
    }
    __syncthreads();
    // write qk into arena rows [x][j]
    #pragma unroll
    for (int xi = 0; xi < 2; xi++) {
        float* row = &arena[(tx*2 + xi)*JSTR + tj*4];
        #pragma unroll
        for (int cc = 0; cc < 6; cc++) {
            ulonglong2 v; v.x = acc[xi][cc*2+0]; v.y = acc[xi][cc*2+1];
            *(ulonglong2*)(row + cc*128) = v;
        }
    }
    __syncthreads();

    // ---- softmax over 225 taps, 16 threads per pixel ----
    {
        int sx = tid >> 4, sub = tid & 15;
        const float* qrow = &arena[sx*JSTR];
        float m = -3.0e38f;
        for (int s = sub; s < WS2; s += 16) {
            int r = s / 15, dx = s - r*15;
            int xx = sx + dx - 7, gy = y + r - 7;
            float val = -1.0e8f;
            if ((unsigned)xx < 32u && (unsigned)gy < 32u)
                val = qrow[r*32 + xx] + qrow[480 + s] + brks[s];
            ashp[s*36 + sx] = val;
            m = fmaxf(m, val);
        }
        m = fmaxf(m, __shfl_xor_sync(0xffffffffu, m, 1));
        m = fmaxf(m, __shfl_xor_sync(0xffffffffu, m, 2));
        m = fmaxf(m, __shfl_xor_sync(0xffffffffu, m, 4));
        m = fmaxf(m, __shfl_xor_sync(0xffffffffu, m, 8));
        float lsum = 0.f;
        for (int s = sub; s < WS2; s += 16) {
            float e = __expf(ashp[s*36 + sx] - m);
            ashp[s*36 + sx] = e;
            lsum += e;
        }
        lsum += __shfl_xor_sync(0xffffffffu, lsum, 1);
        lsum += __shfl_xor_sync(0xffffffffu, lsum, 2);
        lsum += __shfl_xor_sync(0xffffffffu, lsum, 4);
        lsum += __shfl_xor_sync(0xffffffffu, lsum, 8);
        float rinv = 1.0f / lsum;
        for (int s = sub; s < WS2; s += 16) ashp[s*36 + sx] *= rinv;
    }
    __syncthreads();

    // ---- attn global write + V fill (arena reuse, +7 zero-padded rows) ----
    {
        float* aout = attn_out + (size_t)nh*WS2*HW + y*32;
        for (int i = tid; i < WS2*32; i += 512) {
            int s = i >> 5, x2 = i & 31;
            aout[(size_t)s*HW + x2] = ashp[s*36 + x2];
        }
    }
    for (int i = tid; i < 494*8; i += 512) {
        int jj = i >> 3, c4 = (i & 7) * 4;
        float4 f = make_float4(0.f, 0.f, 0.f, 0.f);
        if (jj >= 7 && jj < 487) {
            int j = jj - 7;
            int r = j >> 5, xx = j & 31;
            int gy = y + r - 7;
            if ((unsigned)gy < 32u) f = *(const float4*)&vbase[(size_t)(gy*32 + xx)*HD + c4];
        }
        *(float4*)&arena[jj*36 + c4] = f;
    }
    if (flag) {
        for (int i = tid; i < HD*WS2; i += 512) {
            int c = i / WS2, s = i - c*WS2;
            rvs[s*36 + c] = rel_v[((size_t)h*HD + c)*WS2 + s];
        }
    }
    __syncthreads();

    // ---- pass B: out[c] = sum_taps a * v, split across two 8-warp halves ----
    {
        int xb  = tid & 31;
        int g   = tid >> 5;            // 0..15
        int cgi = g & 7;               // channel group (4 channels)
        int cg4 = cgi * 4;
        int half = g >> 3;             // 0 or 1
        ull a0 = 0ULL, a1 = 0ULL;

        int r_begin = half ? 8 : 0;
        int r_end   = half ? 15 : 8;
        for (int r = r_begin; r < r_end; r++) {
            int gy = y + r - 7;
            if ((unsigned)gy >= 32u) continue;
            const float* ap = &ashp[(r*15)*36 + xb];
            const float* vp = &arena[(r*32 + xb)*36 + cg4];
            #pragma unroll
            for (int dx = 0; dx < 15; dx++) {
                float a = ap[dx*36];
                ull a2 = pk2(a, a);
                ulonglong2 vv = *(const ulonglong2*)(vp + dx*36);
                fma2(a0, a2, vv.x); fma2(a1, a2, vv.y);
            }
        }
        if (flag) {
            int s0 = half ? 112 : 0, s1 = half ? 225 : 112;
            for (int s = s0; s < s1; s++) {
                float a = ashp[s*36 + xb];
                ull a2 = pk2(a, a);
                ulonglong2 rv = *(const ulonglong2*)&rvs[s*36 + cg4];
                fma2(a0, a2, rv.x); fma2(a1, a2, rv.y);
            }
        }
        float* part = qs;   // reuse Qs region: 8*32*4 = 1024 floats
        if (half) {
            ulonglong2 v; v.x = a0; v.y = a1;
            *(ulonglong2*)&part[(cgi*32 + xb)*4] = v;
        }
        __syncthreads();
        if (!half) {
            ulonglong2 pv = *(const ulonglong2*)&part[(cgi*32 + xb)*4];
            float2 p01 = upk(pv.x), p23 = upk(pv.y);
            float2 o01 = upk(a0),  o23 = upk(a1);
            o01.x += p01.x; o01.y += p01.y; o23.x += p23.x; o23.y += p23.y;
            int cfull = h*HD + cg4;
            int rr = (y*32 + xb)*NB + n;
            g_O[(size_t)(cfull+0)*(NB*HW) + rr] = o01.x;
            g_O[(size_t)(cfull+1)*(NB*HW) + rr] = o01.y;
            g_O[(size_t)(cfull+2)*(NB*HW) + rr] = o23.x;
            g_O[(size_t)(cfull+3)*(NB*HW) + rr] = o23.y;
        }
    }
}

// ---------------------------------------------------------------------------
// Final projection: Y[r][o] = Wp[o,:]·O[:,r] + bp[o]. Tile 64o x 32r,
// 256 threads, 2o x 4r microtile. grid (64 r-tiles, 4 o-tiles) = 256 blocks.
// ---------------------------------------------------------------------------
__global__ __launch_bounds__(256) void final_kernel(
    const float* __restrict__ Wp, const float* __restrict__ bp, float* __restrict__ outp)
{
    __shared__ float Xs[64*32];    // [c][r]
    __shared__ float Wso[64*68];   // [o][c]
    const int R = NB*HW;

    int tid = threadIdx.x;
    int to = tid >> 3;
    int tp = tid & 7;
    int r0 = blockIdx.x * 32;
    int o0 = blockIdx.y * 64;

    ull acc[2][2] = {{0ULL,0ULL},{0ULL,0ULL}};

    for (int ck = 0; ck < CC; ck += 64) {
        #pragma unroll
        for (int i = 0; i < 2; i++) {
            int idx = tid + i*256;
            int c = idx >> 3, pp = (idx & 7) * 4;
            *(float4*)&Xs[c*32 + pp] = *(const float4*)&g_O[(size_t)(ck + c)*R + r0 + pp];
        }
        #pragma unroll
        for (int i = 0; i < 4; i++) {
            int idx = tid + i*256;
            int o = idx >> 4, c4 = (idx & 15) * 4;
            *(float4*)&Wso[o*68 + c4] = *(const float4*)&Wp[(size_t)(o0 + o)*CC + ck + c4];
        }
        __syncthreads();
        #pragma unroll 8
        for (int c = 0; c < 64; c++) {
            float w0 = Wso[(to*2+0)*68 + c];
            float w1 = Wso[(to*2+1)*68 + c];
            ulonglong2 xv = *(const ulonglong2*)&Xs[c*32 + tp*4];
            ull wp0 = pk2(w0, w0), wp1 = pk2(w1, w1);
            fma2(acc[0][0], wp0, xv.x); fma2(acc[0][1], wp0, xv.y);
            fma2(acc[1][0], wp1, xv.x); fma2(acc[1][1], wp1, xv.y);
        }
        __syncthreads();
    }

    float res[2][4];
    #pragma unroll
    for (int oi = 0; oi < 2; oi++) {
        float bb = bp[o0 + to*2 + oi];
        float2 p01 = upk(acc[oi][0]), p23 = upk(acc[oi][1]);
        res[oi][0] = p01.x + bb; res[oi][1] = p01.y + bb;
        res[oi][2] = p23.x + bb; res[oi][3] = p23.y + bb;
    }
    int oo = o0 + to*2;
    #pragma unroll
    for (int pj = 0; pj < 4; pj++) {
        int r = r0 + tp*4 + pj;
        float2 f2 = make_float2(res[0][pj], res[1][pj]);
        *(float2*)&outp[(size_t)r*CC + oo] = f2;
    }
}

// ---------------------------------------------------------------------------
extern "C" void kernel_launch(void* const* d_in, const int* in_sizes, int n_in,
                              void* d_out, int out_size)
{
    const float* q     = (const float*)d_in[0];
    const float* k     = (const float*)d_in[1];
    const float* v     = (const float*)d_in[2];
    const float* WQ    = (const float*)d_in[3];
    const float* bQ    = (const float*)d_in[4];
    const float* WK    = (const float*)d_in[5];
    const float* bK    = (const float*)d_in[6];
    const float* WV    = (const float*)d_in[7];
    const float* bV    = (const float*)d_in[8];
    const float* Wrk   = (const float*)d_in[9];
    const float* brk   = (const float*)d_in[10];
    const float* rel_v = (const float*)d_in[11];
    const float* Wp    = (const float*)d_in[12];
    const float* bp    = (const float*)d_in[13];

    float* out = (float*)d_out;
    const int OUT_ELEMS  = HW*NB*CC;
    const int ATTN_ELEMS = NB*NHD*WS2*HW;
    float* attn_out = (out_size >= OUT_ELEMS + ATTN_ELEMS) ? (out + OUT_ELEMS) : nullptr;

    cudaFuncSetAttribute(attn_kernel, cudaFuncAttributeMaxDynamicSharedMemorySize, ATTN_SMEM);

    relv_flag_kernel<<<1, 1024>>>(rel_v);
    proj_kernel<<<dim3(32, 4, 6), 256>>>(q, k, v, WQ, bQ, WK, bK, WV, bV);
    attn_kernel<<<dim3(32, NHD, NB), 512, ATTN_SMEM>>>(Wrk, brk, rel_v, attn_out);
    final_kernel<<<dim3(64, 4), 256>>>(Wp, bp, out);
}

// round 12
// speedup vs baseline: 1.3845x; 1.0118x over previous
#include <cuda_runtime.h>

typedef unsigned long long ull;

#define NB   2
#define CC   256
#define NHD  8
#define HD   32
#define HW   1024
#define WS2  225
#define INVT 0.17677669529663687f

// attention smem layout (floats)
#define JSTR   772                 // arena row stride
#define AR_QS  24704               // Qs [c][x] stride 36 (reused as pass-B partial buffer)
#define AR_ASH 25856               // ash [s][x] stride 36
#define AR_BRK 33956               // brk 225 (pad 240)
#define AR_RVS 34196               // rel_v staged [s][c] stride 36
#define SM_FLOATS 42296
#define ATTN_SMEM (SM_FLOATS*4)    // 169184 B

// Scratch (device globals; allocation-free)
__device__ float g_qT[NB*NHD*HW*HD];   // [nh][p][c]
__device__ float g_kT[NB*NHD*HW*HD];   // [nh][p][c]  (pre-scaled by 1/T)
__device__ float g_vT[NB*NHD*HW*HD];   // [nh][p][c]
__device__ float g_O[CC*NB*HW];        // [c][r], r = p*NB + n
__device__ float g_attn_fallback[NB*NHD*WS2*HW];
__device__ int   g_relv_nz;

// ---- f32x2 helpers -------------------------------------------------------
__device__ __forceinline__ ull pk2(float a, float b) {
    ull r; asm("mov.b64 %0, {%1, %2};" : "=l"(r) : "f"(a), "f"(b)); return r;
}
__device__ __forceinline__ void fma2(ull& d, ull a, ull b) {
    asm("fma.rn.f32x2 %0, %1, %2, %3;" : "=l"(d) : "l"(a), "l"(b), "l"(d));
}
__device__ __forceinline__ float2 upk(ull a) {
    float2 f; asm("mov.b64 {%0, %1}, %2;" : "=f"(f.x), "=f"(f.y) : "l"(a)); return f;
}

// ---------------------------------------------------------------------------
__global__ void relv_flag_kernel(const float* __restrict__ rel_v) {
    const float4* rv4 = (const float4*)rel_v;
    const int total4 = NHD*HD*WS2/4;
    int nz = 0;
    for (int i = threadIdx.x; i < total4; i += blockDim.x) {
        float4 f = rv4[i];
        nz |= (f.x != 0.f) | (f.y != 0.f) | (f.z != 0.f) | (f.w != 0.f);
    }
    int any = __syncthreads_or(nz);
    if (threadIdx.x == 0) g_relv_nz = any;
}

// ---------------------------------------------------------------------------
// Q/K/V projections. Tile 32o x 16p, 128 threads, microtile 2o x 2p (f32x2).
// grid (64 p-tiles, 8 o-tiles, 6 = {q,k,v} x {n}) = 3072 blocks.
// ---------------------------------------------------------------------------
__global__ __launch_bounds__(128) void proj_kernel(
    const float* __restrict__ q, const float* __restrict__ k, const float* __restrict__ v,
    const float* __restrict__ WQ, const float* __restrict__ bQ,
    const float* __restrict__ WK, const float* __restrict__ bK,
    const float* __restrict__ WV, const float* __restrict__ bV)
{
    __shared__ float Xs[64*16];    // [c][p]
    __shared__ float Wso[32*68];   // [o][c] stride 68

    int which = blockIdx.z >> 1;
    int n     = blockIdx.z & 1;
    const float *X, *W, *B; float* out; float scale;
    if (which == 0)      { X = q; W = WQ; B = bQ; out = g_qT; scale = 1.0f; }
    else if (which == 1) { X = k; W = WK; B = bK; out = g_kT; scale = INVT; }
    else                 { X = v; W = WV; B = bV; out = g_vT; scale = 1.0f; }
    X   += (size_t)n * CC * HW;
    out += (size_t)n * NHD * HW * HD;

    int tid = threadIdx.x;
    int to = tid >> 3;            // 0..15 (o pair)
    int tp = tid & 7;             // 0..7  (p pair)
    int p0 = blockIdx.x * 16;
    int o0 = blockIdx.y * 32;

    ull acc0 = 0ULL, acc1 = 0ULL;

    for (int ck = 0; ck < CC; ck += 64) {
        #pragma unroll
        for (int i = 0; i < 2; i++) {
            int idx = tid + i*128;
            int c = idx >> 2, pp = (idx & 3) * 4;
            *(float4*)&Xs[c*16 + pp] = *(const float4*)&X[(size_t)(ck + c)*HW + p0 + pp];
        }
        #pragma unroll
        for (int i = 0; i < 4; i++) {
            int idx = tid + i*128;
            int o = idx >> 4, c4 = (idx & 15) * 4;
            float4 w = *(const float4*)&W[(size_t)(o0 + o)*CC + ck + c4];
            w.x *= scale; w.y *= scale; w.z *= scale; w.w *= scale;
            *(float4*)&Wso[o*68 + c4] = w;
        }
        __syncthreads();
        #pragma unroll 8
        for (int c = 0; c < 64; c++) {
            float w0 = Wso[(to*2+0)*68 + c];
            float w1 = Wso[(to*2+1)*68 + c];
            ull xv = *(const ull*)&Xs[c*16 + tp*2];
            fma2(acc0, pk2(w0, w0), xv);
            fma2(acc1, pk2(w1, w1), xv);
        }
        __syncthreads();
    }

    float bb0 = B[o0 + to*2 + 0] * scale;
    float bb1 = B[o0 + to*2 + 1] * scale;
    float2 r0 = upk(acc0), r1 = upk(acc1);
    int oo = o0 + to*2;
    int h = oo >> 5, c0 = oo & 31;
    {
        int p = p0 + tp*2;
        *(float2*)&out[((size_t)h*HW + p)*HD + c0]     = make_float2(r0.x + bb0, r1.x + bb1);
        *(float2*)&out[((size_t)h*HW + p + 1)*HD + c0] = make_float2(r0.y + bb0, r1.y + bb1);
    }
}

// ---------------------------------------------------------------------------
// Local attention, one block per (y, h, n). 512 threads (16 warps).
// Phase 1: C[32x768] = Q[32x32] x R^T, thread = 4 x-rows x 12 j-cols
//          (tx = tid>>6, tj = tid&63; 3 chunks of 4 j at stride 256).
// Phase 2: band-gather + softmax (16 thr/pixel).
// Phase 3: attn.V, tap-rows split across two 8-warp halves, smem combine.
// ---------------------------------------------------------------------------
__global__ __launch_bounds__(512) void attn_kernel(
    const float* __restrict__ Wrk, const float* __restrict__ brk,
    const float* __restrict__ rel_v, float* __restrict__ attn_out)
{
    extern __shared__ float sm[];
    float* arena = sm;            // R [c][j] -> qk [x][j] -> V [jj][c] (stride 36)
    float* qs    = sm + AR_QS;    // [c][x] stride 36; later pass-B partial buffer
    float* ashp  = sm + AR_ASH;   // [s][x] stride 36
    float* brks  = sm + AR_BRK;
    float* rvs   = sm + AR_RVS;   // [s][c] stride 36

    if (attn_out == nullptr) attn_out = g_attn_fallback;

    int y = blockIdx.x, h = blockIdx.y, n = blockIdx.z;
    int nh = n*NHD + h;
    int tid = threadIdx.x;
    int flag = g_relv_nz;

    const float* qbase = g_qT + ((size_t)nh*HW + (size_t)y*32)*HD;
    const float* kbase = g_kT + (size_t)nh*HW*HD;
    const float* vbase = g_vT + (size_t)nh*HW*HD;

    // Qs [c][x]
    if (tid < 256) {
        int x = tid >> 3, c4 = (tid & 7) * 4;
        float4 f = *(const float4*)&qbase[x*HD + c4];
        qs[(c4+0)*36 + x] = f.x; qs[(c4+1)*36 + x] = f.y;
        qs[(c4+2)*36 + x] = f.z; qs[(c4+3)*36 + x] = f.w;
    }
    // R: K-neighborhood columns j = r*32+xx (zero for invalid rows)
    for (int i = tid; i < 480*8; i += 512) {
        int j = i >> 3, c4 = (i & 7) * 4;
        int r = j >> 5, xx = j & 31;
        int gy = y + r - 7;
        float4 f = make_float4(0.f, 0.f, 0.f, 0.f);
        if ((unsigned)gy < 32u) f = *(const float4*)&kbase[(size_t)(gy*32 + xx)*HD + c4];
        arena[(c4+0)*JSTR + j] = f.x; arena[(c4+1)*JSTR + j] = f.y;
        arena[(c4+2)*JSTR + j] = f.z; arena[(c4+3)*JSTR + j] = f.w;
    }
    // R: Wrk columns j = 480+s
    for (int i = tid; i < WS2*8; i += 512) {
        int s = i >> 3, c4 = (i & 7) * 4;
        float4 f = *(const float4*)&Wrk[((size_t)h*WS2 + s)*HD + c4];
        int j = 480 + s;
        arena[(c4+0)*JSTR + j] = f.x; arena[(c4+1)*JSTR + j] = f.y;
        arena[(c4+2)*JSTR + j] = f.z; arena[(c4+3)*JSTR + j] = f.w;
    }
    if (tid < WS2) brks[tid] = brk[h*WS2 + tid];
    __syncthreads();

    // ---- phase 1 GEMM: tx = 4 x-rows (tid>>6), tj = 12 j-cols (tid&63) ----
    int tx = tid >> 6;       // 0..7
    int tj = tid & 63;       // 0..63
    ull acc[4][6];
    #pragma unroll
    for (int a = 0; a < 4; a++)
        #pragma unroll
        for (int b2 = 0; b2 < 6; b2++) acc[a][b2] = 0ULL;

    #pragma unroll 4
    for (int c = 0; c < 32; c++) {
        float4 qv = *(const float4*)&qs[c*36 + tx*4];
        ull q0 = pk2(qv.x, qv.x), q1 = pk2(qv.y, qv.y);
        ull q2 = pk2(qv.z, qv.z), q3 = pk2(qv.w, qv.w);
        const float* rb = &arena[c*JSTR + tj*4];
        #pragma unroll
        for (int cc = 0; cc < 3; cc++) {
            ulonglong2 rr = *(const ulonglong2*)(rb + cc*256);
            fma2(acc[0][cc*2+0], q0, rr.x); fma2(acc[0][cc*2+1], q0, rr.y);
            fma2(acc[1][cc*2+0], q1, rr.x); fma2(acc[1][cc*2+1], q1, rr.y);
            fma2(acc[2][cc*2+0], q2, rr.x); fma2(acc[2][cc*2+1], q2, rr.y);
            fma2(acc[3][cc*2+0], q3, rr.x); fma2(acc[3][cc*2+1], q3, rr.y);
        }
    }
    __syncthreads();
    // write qk into arena rows [x][j]
    #pragma unroll
    for (int xi = 0; xi < 4; xi++) {
        float* row = &arena[(tx*4 + xi)*JSTR + tj*4];
        #pragma unroll
        for (int cc = 0; cc < 3; cc++) {
            ulonglong2 v; v.x = acc[xi][cc*2+0]; v.y = acc[xi][cc*2+1];
            *(ulonglong2*)(row + cc*256) = v;
        }
    }
    __syncthreads();

    // ---- softmax over 225 taps, 16 threads per pixel ----
    {
        int sx = tid >> 4, sub = tid & 15;
        const float* qrow = &arena[sx*JSTR];
        float m = -3.0e38f;
        for (int s = sub; s < WS2; s += 16) {
            int r = s / 15, dx = s - r*15;
            int xx = sx + dx - 7, gy = y + r - 7;
            float val = -1.0e8f;
            if ((unsigned)xx < 32u && (unsigned)gy < 32u)
                val = qrow[r*32 + xx] + qrow[480 + s] + brks[s];
            ashp[s*36 + sx] = val;
            m = fmaxf(m, val);
        }
        m = fmaxf(m, __shfl_xor_sync(0xffffffffu, m, 1));
        m = fmaxf(m, __shfl_xor_sync(0xffffffffu, m, 2));
        m = fmaxf(m, __shfl_xor_sync(0xffffffffu, m, 4));
        m = fmaxf(m, __shfl_xor_sync(0xffffffffu, m, 8));
        float lsum = 0.f;
        for (int s = sub; s < WS2; s += 16) {
            float e = __expf(ashp[s*36 + sx] - m);
            ashp[s*36 + sx] = e;
            lsum += e;
        }
        lsum += __shfl_xor_sync(0xffffffffu, lsum, 1);
        lsum += __shfl_xor_sync(0xffffffffu, lsum, 2);
        lsum += __shfl_xor_sync(0xffffffffu, lsum, 4);
        lsum += __shfl_xor_sync(0xffffffffu, lsum, 8);
        float rinv = 1.0f / lsum;
        for (int s = sub; s < WS2; s += 16) ashp[s*36 + sx] *= rinv;
    }
    __syncthreads();

    // ---- attn global write + V fill (arena reuse, +7 zero-padded rows) ----
    {
        float* aout = attn_out + (size_t)nh*WS2*HW + y*32;
        for (int i = tid; i < WS2*32; i += 512) {
            int s = i >> 5, x2 = i & 31;
            aout[(size_t)s*HW + x2] = ashp[s*36 + x2];
        }
    }
    for (int i = tid; i < 494*8; i += 512) {
        int jj = i >> 3, c4 = (i & 7) * 4;
        float4 f = make_float4(0.f, 0.f, 0.f, 0.f);
        if (jj >= 7 && jj < 487) {
            int j = jj - 7;
            int r = j >> 5, xx = j & 31;
            int gy = y + r - 7;
            if ((unsigned)gy < 32u) f = *(const float4*)&vbase[(size_t)(gy*32 + xx)*HD + c4];
        }
        *(float4*)&arena[jj*36 + c4] = f;
    }
    if (flag) {
        for (int i = tid; i < HD*WS2; i += 512) {
            int c = i / WS2, s = i - c*WS2;
            rvs[s*36 + c] = rel_v[((size_t)h*HD + c)*WS2 + s];
        }
    }
    __syncthreads();

    // ---- pass B: out[c] = sum_taps a * v, split across two 8-warp halves ----
    {
        int xb  = tid & 31;
        int g   = tid >> 5;            // 0..15
        int cgi = g & 7;               // channel group (4 channels)
        int cg4 = cgi * 4;
        int half = g >> 3;             // 0 or 1
        ull a0 = 0ULL, a1 = 0ULL;

        int r_begin = half ? 8 : 0;
        int r_end   = half ? 15 : 8;
        for (int r = r_begin; r < r_end; r++) {
            int gy = y + r - 7;
            if ((unsigned)gy >= 32u) continue;
            const float* ap = &ashp[(r*15)*36 + xb];
            const float* vp = &arena[(r*32 + xb)*36 + cg4];
            #pragma unroll
            for (int dx = 0; dx < 15; dx++) {
                float a = ap[dx*36];
                ull a2 = pk2(a, a);
                ulonglong2 vv = *(const ulonglong2*)(vp + dx*36);
                fma2(a0, a2, vv.x); fma2(a1, a2, vv.y);
            }
        }
        if (flag) {
            int s0 = half ? 112 : 0, s1 = half ? 225 : 112;
            for (int s = s0; s < s1; s++) {
                float a = ashp[s*36 + xb];
                ull a2 = pk2(a, a);
                ulonglong2 rv = *(const ulonglong2*)&rvs[s*36 + cg4];
                fma2(a0, a2, rv.x); fma2(a1, a2, rv.y);
            }
        }
        float* part = qs;   // reuse Qs region: 8*32*4 = 1024 floats
        if (half) {
            ulonglong2 v; v.x = a0; v.y = a1;
            *(ulonglong2*)&part[(cgi*32 + xb)*4] = v;
        }
        __syncthreads();
        if (!half) {
            ulonglong2 pv = *(const ulonglong2*)&part[(cgi*32 + xb)*4];
            float2 p01 = upk(pv.x), p23 = upk(pv.y);
            float2 o01 = upk(a0),  o23 = upk(a1);
            o01.x += p01.x; o01.y += p01.y; o23.x += p23.x; o23.y += p23.y;
            int cfull = h*HD + cg4;
            int rr = (y*32 + xb)*NB + n;
            g_O[(size_t)(cfull+0)*(NB*HW) + rr] = o01.x;
            g_O[(size_t)(cfull+1)*(NB*HW) + rr] = o01.y;
            g_O[(size_t)(cfull+2)*(NB*HW) + rr] = o23.x;
            g_O[(size_t)(cfull+3)*(NB*HW) + rr] = o23.y;
        }
    }
}

// ---------------------------------------------------------------------------
// Final projection: tile 32o x 16r, 128 threads, 2o x 2r microtile.
// grid (128 r-tiles, 8 o-tiles) = 1024 blocks.
// ---------------------------------------------------------------------------
__global__ __launch_bounds__(128) void final_kernel(
    const float* __restrict__ Wp, const float* __restrict__ bp, float* __restrict__ outp)
{
    __shared__ float Xs[64*16];    // [c][r]
    __shared__ float Wso[32*68];   // [o][c]
    const int R = NB*HW;

    int tid = threadIdx.x;
    int to = tid >> 3;
    int tp = tid & 7;
    int r0 = blockIdx.x * 16;
    int o0 = blockIdx.y * 32;

    ull acc0 = 0ULL, acc1 = 0ULL;

    for (int ck = 0; ck < CC; ck += 64) {
        #pragma unroll
        for (int i = 0; i < 2; i++) {
            int idx = tid + i*128;
            int c = idx >> 2, pp = (idx & 3) * 4;
            *(float4*)&Xs[c*16 + pp] = *(const float4*)&g_O[(size_t)(ck + c)*R + r0 + pp];
        }
        #pragma unroll
        for (int i = 0; i < 4; i++) {
            int idx = tid + i*128;
            int o = idx >> 4, c4 = (idx & 15) * 4;
            *(float4*)&Wso[o*68 + c4] = *(const float4*)&Wp[(size_t)(o0 + o)*CC + ck + c4];
        }
        __syncthreads();
        #pragma unroll 8
        for (int c = 0; c < 64; c++) {
            float w0 = Wso[(to*2+0)*68 + c];
            float w1 = Wso[(to*2+1)*68 + c];
            ull xv = *(const ull*)&Xs[c*16 + tp*2];
            fma2(acc0, pk2(w0, w0), xv);
            fma2(acc1, pk2(w1, w1), xv);
        }
        __syncthreads();
    }

    float bb0 = bp[o0 + to*2 + 0];
    float bb1 = bp[o0 + to*2 + 1];
    float2 r0v = upk(acc0), r1v = upk(acc1);
    int oo = o0 + to*2;
    int r = r0 + tp*2;
    *(float2*)&outp[(size_t)(r    )*CC + oo] = make_float2(r0v.x + bb0, r1v.x + bb1);
    *(float2*)&outp[(size_t)(r + 1)*CC + oo] = make_float2(r0v.y + bb0, r1v.y + bb1);
}

// ---------------------------------------------------------------------------
extern "C" void kernel_launch(void* const* d_in, const int* in_sizes, int n_in,
                              void* d_out, int out_size)
{
    const float* q     = (const float*)d_in[0];
    const float* k     = (const float*)d_in[1];
    const float* v     = (const float*)d_in[2];
    const float* WQ    = (const float*)d_in[3];
    const float* bQ    = (const float*)d_in[4];
    const float* WK    = (const float*)d_in[5];
    const float* bK    = (const float*)d_in[6];
    const float* WV    = (const float*)d_in[7];
    const float* bV    = (const float*)d_in[8];
    const float* Wrk   = (const float*)d_in[9];
    const float* brk   = (const float*)d_in[10];
    const float* rel_v = (const float*)d_in[11];
    const float* Wp    = (const float*)d_in[12];
    const float* bp    = (const float*)d_in[13];

    float* out = (float*)d_out;
    const int OUT_ELEMS  = HW*NB*CC;
    const int ATTN_ELEMS = NB*NHD*WS2*HW;
    float* attn_out = (out_size >= OUT_ELEMS + ATTN_ELEMS) ? (out + OUT_ELEMS) : nullptr;

    cudaFuncSetAttribute(attn_kernel, cudaFuncAttributeMaxDynamicSharedMemorySize, ATTN_SMEM);

    relv_flag_kernel<<<1, 1024>>>(rel_v);
    proj_kernel<<<dim3(64, 8, 6), 128>>>(q, k, v, WQ, bQ, WK, bK, WV, bV);
    attn_kernel<<<dim3(32, NHD, NB), 512, ATTN_SMEM>>>(Wrk, brk, rel_v, attn_out);
    final_kernel<<<dim3(128, 8), 128>>>(Wp, bp, out);
}